// round 13
// baseline (speedup 1.0000x reference)
#include <cuda_runtime.h>
#include <cuda_fp16.h>
#include <mma.h>
#include <cstdint>

using namespace nvcuda;

#define F1 128
#define F2 64
#define MAX_NODES 100000
#define MAX_EDGES 3200000

// ---------------------------------------------------------------------------
// Device-global scratch (allocation-free per harness rules)
// ---------------------------------------------------------------------------
__device__ __half g_y[(size_t)MAX_NODES * F1];
__device__ float g_h[(size_t)MAX_NODES * F1];
__device__ unsigned long long g_edges[MAX_EDGES]; // packed (col, val) sorted by row
__device__ int g_cnt[MAX_NODES];
__device__ int g_ptrE[MAX_NODES];
__device__ int g_bsum[128];
__device__ int g_ptr[MAX_NODES + 1];
__device__ int g_work[MAX_NODES];

// ---------------------------------------------------------------------------
// CSR build: zero counts -> histogram -> scan1 -> scan23 -> scatter
// ---------------------------------------------------------------------------
__global__ __launch_bounds__(256) void zero_cnt_kernel(int n_nodes) {
    int i = blockIdx.x * 256 + threadIdx.x;
    if (i < n_nodes) g_cnt[i] = 0;
}

__global__ __launch_bounds__(256) void hist_kernel(const int* __restrict__ rows,
                                                   int n_edges) {
    int e = blockIdx.x * 256 + threadIdx.x;
    if (e < n_edges) atomicAdd(&g_cnt[__ldg(rows + e)], 1);
}

// Exclusive scan of 1024 elements per block (256 threads x 4).
__global__ __launch_bounds__(256) void scan1_kernel(int n) {
    __shared__ int s[256];
    const int t = threadIdx.x;
    const int base = blockIdx.x * 1024 + t * 4;
    int v[4];
#pragma unroll
    for (int j = 0; j < 4; j++) v[j] = (base + j < n) ? g_cnt[base + j] : 0;
    int tsum = v[0] + v[1] + v[2] + v[3];
    s[t] = tsum;
    __syncthreads();
    for (int off = 1; off < 256; off <<= 1) {
        int x = 0;
        if (t >= off) x = s[t - off];
        __syncthreads();
        if (t >= off) s[t] += x;
        __syncthreads();
    }
    int run = s[t] - tsum;  // exclusive
#pragma unroll
    for (int j = 0; j < 4; j++) {
        if (base + j < n) g_ptrE[base + j] = run;
        run += v[j];
    }
    if (t == 255) g_bsum[blockIdx.x] = s[255];
}

// Merged scan2+scan3: every block re-scans the (<=128) chunk sums in smem,
// then combines with the per-chunk exclusive scan -> row ptrs + cursors.
__global__ __launch_bounds__(256) void scan23_kernel(int n_nodes, int n_edges,
                                                     int nb_scan) {
    __shared__ int sb[128];
    const int t = threadIdx.x;
    if (t < 128) sb[t] = (t < nb_scan) ? g_bsum[t] : 0;
    __syncthreads();
    for (int off = 1; off < 128; off <<= 1) {
        int x = 0;
        if (t < 128 && t >= off) x = sb[t - off];
        __syncthreads();
        if (t < 128 && t >= off) sb[t] += x;
        __syncthreads();
    }
    // sb is now an inclusive scan; exclusive prefix of chunk c = sb[c-1]
    const int i = blockIdx.x * 256 + t;
    if (i < n_nodes) {
        const int c = i >> 10;
        const int b = (c == 0) ? 0 : sb[c - 1];
        const int p = g_ptrE[i] + b;
        g_ptr[i] = p;
        g_work[i] = p;
    }
    if (i == 0) g_ptr[n_nodes] = n_edges;
}

__global__ __launch_bounds__(256) void scatter_kernel(const int* __restrict__ rows,
                                                      const int* __restrict__ cols,
                                                      const float* __restrict__ vals,
                                                      int n_edges) {
    int e = blockIdx.x * 256 + threadIdx.x;
    if (e < n_edges) {
        int r = __ldg(rows + e);
        int pos = atomicAdd(&g_work[r], 1);
        unsigned long long packed =
            (unsigned long long)(unsigned int)__ldg(cols + e) |
            ((unsigned long long)__float_as_uint(__ldg(vals + e)) << 32);
        g_edges[pos] = packed;
    }
}

// ---------------------------------------------------------------------------
// Pull-based CSR SPMM from fp16 source, fp32 accumulation. One warp per row,
// 4-edge unroll for MLP=4 against L2 gather latency. Rows [row0, row0+nrows).
// ---------------------------------------------------------------------------
__global__ __launch_bounds__(256) void csr_spmm128_kernel(const __half* __restrict__ src,
                                                          float* __restrict__ dst,
                                                          int row0, int nrows) {
    const int lane = threadIdx.x & 31;
    const int idx = (blockIdx.x * 256 + threadIdx.x) >> 5;
    if (idx >= nrows) return;
    const int row = row0 + idx;
    const int p0 = __ldg(&g_ptr[row]);
    const int p1 = __ldg(&g_ptr[row + 1]);
    const uint2* s8 = reinterpret_cast<const uint2*>(src);

    float4 acc = make_float4(0.f, 0.f, 0.f, 0.f);
    int e = p0;
    for (; e + 4 <= p1; e += 4) {
        unsigned long long w[4];
#pragma unroll
        for (int j = 0; j < 4; j++) w[j] = __ldg(&g_edges[e + j]);
        uint2 g[4];
#pragma unroll
        for (int j = 0; j < 4; j++)
            g[j] = __ldg(s8 + (size_t)(unsigned int)w[j] * 32 + lane);
#pragma unroll
        for (int j = 0; j < 4; j++) {
            float v = __uint_as_float((unsigned int)(w[j] >> 32));
            float2 f01 = __half22float2(*reinterpret_cast<__half2*>(&g[j].x));
            float2 f23 = __half22float2(*reinterpret_cast<__half2*>(&g[j].y));
            acc.x = fmaf(f01.x, v, acc.x);
            acc.y = fmaf(f01.y, v, acc.y);
            acc.z = fmaf(f23.x, v, acc.z);
            acc.w = fmaf(f23.y, v, acc.w);
        }
    }
    for (; e < p1; e++) {
        unsigned long long w = __ldg(&g_edges[e]);
        float v = __uint_as_float((unsigned int)(w >> 32));
        uint2 g = __ldg(s8 + (size_t)(unsigned int)w * 32 + lane);
        float2 f01 = __half22float2(*reinterpret_cast<__half2*>(&g.x));
        float2 f23 = __half22float2(*reinterpret_cast<__half2*>(&g.y));
        acc.x = fmaf(f01.x, v, acc.x);
        acc.y = fmaf(f01.y, v, acc.y);
        acc.z = fmaf(f23.x, v, acc.z);
        acc.w = fmaf(f23.y, v, acc.w);
    }
    reinterpret_cast<float4*>(dst)[(size_t)row * 32 + lane] = acc;
}

__global__ __launch_bounds__(256) void csr_spmm64_kernel(const __half* __restrict__ src,
                                                         const float* __restrict__ b2,
                                                         float* __restrict__ dst,
                                                         int n_nodes) {
    const int lane = threadIdx.x & 31;
    const int row = (blockIdx.x * 256 + threadIdx.x) >> 5;
    if (row >= n_nodes) return;
    const int p0 = __ldg(&g_ptr[row]);
    const int p1 = __ldg(&g_ptr[row + 1]);
    const unsigned* s4 = reinterpret_cast<const unsigned*>(src);

    float2 acc = make_float2(0.f, 0.f);
    int e = p0;
    for (; e + 4 <= p1; e += 4) {
        unsigned long long w[4];
#pragma unroll
        for (int j = 0; j < 4; j++) w[j] = __ldg(&g_edges[e + j]);
        unsigned g[4];
#pragma unroll
        for (int j = 0; j < 4; j++)
            g[j] = __ldg(s4 + (size_t)(unsigned int)w[j] * 32 + lane);
#pragma unroll
        for (int j = 0; j < 4; j++) {
            float v = __uint_as_float((unsigned int)(w[j] >> 32));
            float2 f = __half22float2(*reinterpret_cast<__half2*>(&g[j]));
            acc.x = fmaf(f.x, v, acc.x);
            acc.y = fmaf(f.y, v, acc.y);
        }
    }
    for (; e < p1; e++) {
        unsigned long long w = __ldg(&g_edges[e]);
        float v = __uint_as_float((unsigned int)(w >> 32));
        unsigned g = __ldg(s4 + (size_t)(unsigned int)w * 32 + lane);
        float2 f = __half22float2(*reinterpret_cast<__half2*>(&g));
        acc.x = fmaf(f.x, v, acc.x);
        acc.y = fmaf(f.y, v, acc.y);
    }
    float2 bv = __ldg(reinterpret_cast<const float2*>(b2) + lane);
    acc.x += bv.x;
    acc.y += bv.y;
    reinterpret_cast<float2*>(dst)[(size_t)row * 32 + lane] = acc;
}

// ---------------------------------------------------------------------------
// Tensor-core GEMM (wmma m16n16k16, fp16 in / fp32 acc)
// ---------------------------------------------------------------------------
template <int K, int N, bool RELU_BIAS>
__global__ __launch_bounds__(256) void wmma_gemm_kernel(const float* __restrict__ A,
                                                        const float* __restrict__ W,
                                                        const float* __restrict__ bias,
                                                        __half* __restrict__ Yh,
                                                        int n_rows) {
    constexpr int BM = 128;
    constexpr int BK = 64;
    constexpr int BN = N;
    constexpr int LDA = BK + 8;
    constexpr int LDB = BN + 8;
    constexpr int WN = BN / 32;
    constexpr int WM = 2;

    __shared__ __half As[BM][LDA];
    __shared__ __half Bs[BK][LDB];
    __shared__ float St[8][16][20];

    const int t = threadIdx.x;
    const int warp = t >> 5;
    const int lane = t & 31;
    const int row0 = blockIdx.x * BM;
    const int warpM = warp & 3;
    const int warpN = warp >> 2;

    wmma::fragment<wmma::accumulator, 16, 16, 16, float> acc[WM][WN];
#pragma unroll
    for (int mi = 0; mi < WM; mi++)
#pragma unroll
        for (int ni = 0; ni < WN; ni++) wmma::fill_fragment(acc[mi][ni], 0.0f);

    for (int k0 = 0; k0 < K; k0 += BK) {
        {
            const int quad = t & 15;
            const int rsub = t >> 4;
#pragma unroll
            for (int p = 0; p < BM / 16; p++) {
                const int row = p * 16 + rsub;
                const int grow = row0 + row;
                float4 av = make_float4(0.f, 0.f, 0.f, 0.f);
                if (grow < n_rows)
                    av = *reinterpret_cast<const float4*>(A + (size_t)grow * K + k0 + quad * 4);
                if (RELU_BIAS) {
                    float4 bv = *reinterpret_cast<const float4*>(bias + k0 + quad * 4);
                    av.x = fmaxf(av.x + bv.x, 0.f);
                    av.y = fmaxf(av.y + bv.y, 0.f);
                    av.z = fmaxf(av.z + bv.z, 0.f);
                    av.w = fmaxf(av.w + bv.w, 0.f);
                }
                __half2 h01 = __float22half2_rn(make_float2(av.x, av.y));
                __half2 h23 = __float22half2_rn(make_float2(av.z, av.w));
                uint2 o;
                o.x = *reinterpret_cast<unsigned*>(&h01);
                o.y = *reinterpret_cast<unsigned*>(&h23);
                *reinterpret_cast<uint2*>(&As[row][quad * 4]) = o;
            }
        }
        {
            constexpr int QPR = BN / 4;
            constexpr int RPP = 256 / QPR;
            const int quad = t % QPR;
            const int rsub = t / QPR;
#pragma unroll
            for (int p = 0; p < BK / RPP; p++) {
                const int row = p * RPP + rsub;
                float4 wv = *reinterpret_cast<const float4*>(W + (size_t)(k0 + row) * BN + quad * 4);
                __half2 h01 = __float22half2_rn(make_float2(wv.x, wv.y));
                __half2 h23 = __float22half2_rn(make_float2(wv.z, wv.w));
                uint2 o;
                o.x = *reinterpret_cast<unsigned*>(&h01);
                o.y = *reinterpret_cast<unsigned*>(&h23);
                *reinterpret_cast<uint2*>(&Bs[row][quad * 4]) = o;
            }
        }
        __syncthreads();

#pragma unroll
        for (int kk = 0; kk < BK; kk += 16) {
            wmma::fragment<wmma::matrix_a, 16, 16, 16, __half, wmma::row_major> af[WM];
            wmma::fragment<wmma::matrix_b, 16, 16, 16, __half, wmma::row_major> bf[WN];
#pragma unroll
            for (int mi = 0; mi < WM; mi++)
                wmma::load_matrix_sync(af[mi], &As[warpM * 32 + mi * 16][kk], LDA);
#pragma unroll
            for (int ni = 0; ni < WN; ni++)
                wmma::load_matrix_sync(bf[ni], &Bs[kk][warpN * (BN / 2) + ni * 16], LDB);
#pragma unroll
            for (int mi = 0; mi < WM; mi++)
#pragma unroll
                for (int ni = 0; ni < WN; ni++)
                    wmma::mma_sync(acc[mi][ni], af[mi], bf[ni], acc[mi][ni]);
        }
        __syncthreads();
    }

#pragma unroll
    for (int mi = 0; mi < WM; mi++) {
#pragma unroll
        for (int ni = 0; ni < WN; ni++) {
            wmma::store_matrix_sync(&St[warp][0][0], acc[mi][ni], 20, wmma::mem_row_major);
            __syncwarp();
            const int r = lane >> 1;
            const int cq = (lane & 1) * 8;
            const int grow = row0 + warpM * 32 + mi * 16 + r;
            if (grow < n_rows) {
                float* sp = &St[warp][r][cq];
                __half2 h0 = __float22half2_rn(make_float2(sp[0], sp[1]));
                __half2 h1 = __float22half2_rn(make_float2(sp[2], sp[3]));
                __half2 h2 = __float22half2_rn(make_float2(sp[4], sp[5]));
                __half2 h3 = __float22half2_rn(make_float2(sp[6], sp[7]));
                uint4 o;
                o.x = *reinterpret_cast<unsigned*>(&h0);
                o.y = *reinterpret_cast<unsigned*>(&h1);
                o.z = *reinterpret_cast<unsigned*>(&h2);
                o.w = *reinterpret_cast<unsigned*>(&h3);
                const int gcol = warpN * (BN / 2) + ni * 16 + cq;
                *reinterpret_cast<uint4*>(Yh + (size_t)grow * N + gcol) = o;
            }
            __syncwarp();
        }
    }
}

// ---------------------------------------------------------------------------
// launch: gemm1 forked vs CSR chain; gemm2(chunk0) overlapped with
// spmm1(chunk1) via the side stream.
// ---------------------------------------------------------------------------
extern "C" void kernel_launch(void* const* d_in, const int* in_sizes, int n_in,
                              void* d_out, int out_size) {
    const float* x = (const float*)d_in[0];
    const int* adj_rows = (const int*)d_in[1];
    const int* adj_cols = (const int*)d_in[2];
    const float* adj_vals = (const float*)d_in[3];
    const float* W1 = (const float*)d_in[4];
    const float* b1 = (const float*)d_in[5];
    const float* W2 = (const float*)d_in[6];
    const float* b2 = (const float*)d_in[7];
    float* out = (float*)d_out;

    const int n_nodes = in_sizes[0] / 256;
    const int n_edges = in_sizes[1];

    void* yp_ = nullptr;
    void* hp_ = nullptr;
    cudaGetSymbolAddress(&yp_, g_y);
    cudaGetSymbolAddress(&hp_, g_h);
    __half* y = (__half*)yp_;
    float* h = (float*)hp_;
    __half* z = y;  // reuse g_y (fp16) for z after spmm1 consumed y

    static cudaStream_t side = [] {
        cudaStream_t s;
        cudaStreamCreateWithFlags(&s, cudaStreamNonBlocking);
        return s;
    }();
    static cudaEvent_t evFork = [] {
        cudaEvent_t e;
        cudaEventCreateWithFlags(&e, cudaEventDisableTiming);
        return e;
    }();
    static cudaEvent_t evJoin = [] {
        cudaEvent_t e;
        cudaEventCreateWithFlags(&e, cudaEventDisableTiming);
        return e;
    }();
    static cudaEvent_t evH0 = [] {
        cudaEvent_t e;
        cudaEventCreateWithFlags(&e, cudaEventDisableTiming);
        return e;
    }();
    static cudaEvent_t evZ0 = [] {
        cudaEvent_t e;
        cudaEventCreateWithFlags(&e, cudaEventDisableTiming);
        return e;
    }();

    const int nb_scan = (n_nodes + 1023) / 1024;
    const int eb = (n_edges + 255) / 256;
    const int nb_nodes = (n_nodes + 255) / 256;

    // 128-aligned row split for the spmm1/gemm2 pipeline
    const int c0 = ((n_nodes / 2 + 127) / 128) * 128;   // chunk0 rows
    const int c1 = n_nodes - c0;                        // chunk1 rows

    // fork: gemm1 on 'side', concurrent with the CSR chain on stream 0
    cudaEventRecord(evFork, 0);
    cudaStreamWaitEvent(side, evFork, 0);
    wmma_gemm_kernel<256, F1, false>
        <<<(n_nodes + 127) / 128, 256, 0, side>>>(x, W1, nullptr, y, n_nodes);
    cudaEventRecord(evJoin, side);

    // CSR chain (stream 0)
    zero_cnt_kernel<<<nb_nodes, 256>>>(n_nodes);
    hist_kernel<<<eb, 256>>>(adj_rows, n_edges);
    scan1_kernel<<<nb_scan, 256>>>(n_nodes);
    scan23_kernel<<<nb_nodes + 1, 256>>>(n_nodes, n_edges, nb_scan);
    scatter_kernel<<<eb, 256>>>(adj_rows, adj_cols, adj_vals, n_edges);

    // join: spmm1 needs both y (side) and CSR (stream 0)
    cudaStreamWaitEvent(0, evJoin, 0);

    // spmm1 chunk0, then fork gemm2(chunk0) to side while spmm1 chunk1 runs
    csr_spmm128_kernel<<<(c0 * 32 + 255) / 256, 256>>>(y, h, 0, c0);
    cudaEventRecord(evH0, 0);
    cudaStreamWaitEvent(side, evH0, 0);
    wmma_gemm_kernel<F1, F2, true>
        <<<(c0 + 127) / 128, 256, 0, side>>>(h, W2, b1, z, c0);
    cudaEventRecord(evZ0, side);

    csr_spmm128_kernel<<<(c1 * 32 + 255) / 256, 256>>>(y, h, c0, c1);
    // gemm2 chunk1 (row-offset pointers; 128-row alignment keeps tiles intact)
    wmma_gemm_kernel<F1, F2, true><<<(c1 + 127) / 128, 256>>>(
        h + (size_t)c0 * F1, W2, b1, z + (size_t)c0 * F2, c1);

    // join gemm2 chunk0, then final spmm
    cudaStreamWaitEvent(0, evZ0, 0);
    csr_spmm64_kernel<<<(n_nodes * 32 + 255) / 256, 256>>>(z, b2, out, n_nodes);
}

// round 14
// speedup vs baseline: 1.0109x; 1.0109x over previous
#include <cuda_runtime.h>
#include <cuda_fp16.h>
#include <mma.h>
#include <cstdint>

using namespace nvcuda;

#define F1 128
#define F2 64
#define MAX_NODES 100000
#define MAX_EDGES 3200000

// ---------------------------------------------------------------------------
// Device-global scratch (allocation-free per harness rules)
// ---------------------------------------------------------------------------
__device__ __half g_y[(size_t)MAX_NODES * F1];
__device__ float g_h[(size_t)MAX_NODES * F1];
__device__ unsigned long long g_edges[MAX_EDGES]; // packed (col, val) sorted by row
__device__ int g_cnt[MAX_NODES];
__device__ int g_ptrE[MAX_NODES];
__device__ int g_bsum[128];
__device__ int g_ptr[MAX_NODES + 1];
__device__ int g_work[MAX_NODES];

// ---------------------------------------------------------------------------
// CSR build: zero counts -> histogram -> scan1 -> scan23 -> scatter
// ---------------------------------------------------------------------------
__global__ __launch_bounds__(256) void zero_cnt_kernel(int n_nodes) {
    int i = blockIdx.x * 256 + threadIdx.x;
    if (i < n_nodes) g_cnt[i] = 0;
}

__global__ __launch_bounds__(256) void hist_kernel(const int* __restrict__ rows,
                                                   int n_edges) {
    int e = blockIdx.x * 256 + threadIdx.x;
    if (e < n_edges) atomicAdd(&g_cnt[__ldg(rows + e)], 1);
}

// Exclusive scan of 1024 elements per block (256 threads x 4).
__global__ __launch_bounds__(256) void scan1_kernel(int n) {
    __shared__ int s[256];
    const int t = threadIdx.x;
    const int base = blockIdx.x * 1024 + t * 4;
    int v[4];
#pragma unroll
    for (int j = 0; j < 4; j++) v[j] = (base + j < n) ? g_cnt[base + j] : 0;
    int tsum = v[0] + v[1] + v[2] + v[3];
    s[t] = tsum;
    __syncthreads();
    for (int off = 1; off < 256; off <<= 1) {
        int x = 0;
        if (t >= off) x = s[t - off];
        __syncthreads();
        if (t >= off) s[t] += x;
        __syncthreads();
    }
    int run = s[t] - tsum;  // exclusive
#pragma unroll
    for (int j = 0; j < 4; j++) {
        if (base + j < n) g_ptrE[base + j] = run;
        run += v[j];
    }
    if (t == 255) g_bsum[blockIdx.x] = s[255];
}

// Merged scan2+scan3: every block re-scans the (<=128) chunk sums in smem,
// then combines with the per-chunk exclusive scan -> row ptrs + cursors.
__global__ __launch_bounds__(256) void scan23_kernel(int n_nodes, int n_edges,
                                                     int nb_scan) {
    __shared__ int sb[128];
    const int t = threadIdx.x;
    if (t < 128) sb[t] = (t < nb_scan) ? g_bsum[t] : 0;
    __syncthreads();
    for (int off = 1; off < 128; off <<= 1) {
        int x = 0;
        if (t < 128 && t >= off) x = sb[t - off];
        __syncthreads();
        if (t < 128 && t >= off) sb[t] += x;
        __syncthreads();
    }
    // sb is now an inclusive scan; exclusive prefix of chunk c = sb[c-1]
    const int i = blockIdx.x * 256 + t;
    if (i < n_nodes) {
        const int c = i >> 10;
        const int b = (c == 0) ? 0 : sb[c - 1];
        const int p = g_ptrE[i] + b;
        g_ptr[i] = p;
        g_work[i] = p;
    }
    if (i == 0) g_ptr[n_nodes] = n_edges;
}

__global__ __launch_bounds__(256) void scatter_kernel(const int* __restrict__ rows,
                                                      const int* __restrict__ cols,
                                                      const float* __restrict__ vals,
                                                      int n_edges) {
    int e = blockIdx.x * 256 + threadIdx.x;
    if (e < n_edges) {
        int r = __ldg(rows + e);
        int pos = atomicAdd(&g_work[r], 1);
        unsigned long long packed =
            (unsigned long long)(unsigned int)__ldg(cols + e) |
            ((unsigned long long)__float_as_uint(__ldg(vals + e)) << 32);
        g_edges[pos] = packed;
    }
}

// ---------------------------------------------------------------------------
// Pull-based CSR SPMM from fp16 source, fp32 accumulation. One warp per row,
// 4-edge unroll for MLP=4 against L2 gather latency.
// ---------------------------------------------------------------------------
__global__ __launch_bounds__(256) void csr_spmm128_kernel(const __half* __restrict__ src,
                                                          float* __restrict__ dst,
                                                          int n_nodes) {
    const int lane = threadIdx.x & 31;
    const int row = (blockIdx.x * 256 + threadIdx.x) >> 5;
    if (row >= n_nodes) return;
    const int p0 = __ldg(&g_ptr[row]);
    const int p1 = __ldg(&g_ptr[row + 1]);
    const uint2* s8 = reinterpret_cast<const uint2*>(src);

    float4 acc = make_float4(0.f, 0.f, 0.f, 0.f);
    int e = p0;
    for (; e + 4 <= p1; e += 4) {
        unsigned long long w[4];
#pragma unroll
        for (int j = 0; j < 4; j++) w[j] = __ldg(&g_edges[e + j]);
        uint2 g[4];
#pragma unroll
        for (int j = 0; j < 4; j++)
            g[j] = __ldg(s8 + (size_t)(unsigned int)w[j] * 32 + lane);
#pragma unroll
        for (int j = 0; j < 4; j++) {
            float v = __uint_as_float((unsigned int)(w[j] >> 32));
            float2 f01 = __half22float2(*reinterpret_cast<__half2*>(&g[j].x));
            float2 f23 = __half22float2(*reinterpret_cast<__half2*>(&g[j].y));
            acc.x = fmaf(f01.x, v, acc.x);
            acc.y = fmaf(f01.y, v, acc.y);
            acc.z = fmaf(f23.x, v, acc.z);
            acc.w = fmaf(f23.y, v, acc.w);
        }
    }
    for (; e < p1; e++) {
        unsigned long long w = __ldg(&g_edges[e]);
        float v = __uint_as_float((unsigned int)(w >> 32));
        uint2 g = __ldg(s8 + (size_t)(unsigned int)w * 32 + lane);
        float2 f01 = __half22float2(*reinterpret_cast<__half2*>(&g.x));
        float2 f23 = __half22float2(*reinterpret_cast<__half2*>(&g.y));
        acc.x = fmaf(f01.x, v, acc.x);
        acc.y = fmaf(f01.y, v, acc.y);
        acc.z = fmaf(f23.x, v, acc.z);
        acc.w = fmaf(f23.y, v, acc.w);
    }
    reinterpret_cast<float4*>(dst)[(size_t)row * 32 + lane] = acc;
}

__global__ __launch_bounds__(256) void csr_spmm64_kernel(const __half* __restrict__ src,
                                                         const float* __restrict__ b2,
                                                         float* __restrict__ dst,
                                                         int n_nodes) {
    const int lane = threadIdx.x & 31;
    const int row = (blockIdx.x * 256 + threadIdx.x) >> 5;
    if (row >= n_nodes) return;
    const int p0 = __ldg(&g_ptr[row]);
    const int p1 = __ldg(&g_ptr[row + 1]);
    const unsigned* s4 = reinterpret_cast<const unsigned*>(src);

    float2 acc = make_float2(0.f, 0.f);
    int e = p0;
    for (; e + 4 <= p1; e += 4) {
        unsigned long long w[4];
#pragma unroll
        for (int j = 0; j < 4; j++) w[j] = __ldg(&g_edges[e + j]);
        unsigned g[4];
#pragma unroll
        for (int j = 0; j < 4; j++)
            g[j] = __ldg(s4 + (size_t)(unsigned int)w[j] * 32 + lane);
#pragma unroll
        for (int j = 0; j < 4; j++) {
            float v = __uint_as_float((unsigned int)(w[j] >> 32));
            float2 f = __half22float2(*reinterpret_cast<__half2*>(&g[j]));
            acc.x = fmaf(f.x, v, acc.x);
            acc.y = fmaf(f.y, v, acc.y);
        }
    }
    for (; e < p1; e++) {
        unsigned long long w = __ldg(&g_edges[e]);
        float v = __uint_as_float((unsigned int)(w >> 32));
        unsigned g = __ldg(s4 + (size_t)(unsigned int)w * 32 + lane);
        float2 f = __half22float2(*reinterpret_cast<__half2*>(&g));
        acc.x = fmaf(f.x, v, acc.x);
        acc.y = fmaf(f.y, v, acc.y);
    }
    float2 bv = __ldg(reinterpret_cast<const float2*>(b2) + lane);
    acc.x += bv.x;
    acc.y += bv.y;
    reinterpret_cast<float2*>(dst)[(size_t)row * 32 + lane] = acc;
}

// ---------------------------------------------------------------------------
// Tensor-core GEMM (wmma m16n16k16, fp16 in / fp32 acc)
// ---------------------------------------------------------------------------
template <int K, int N, bool RELU_BIAS>
__global__ __launch_bounds__(256) void wmma_gemm_kernel(const float* __restrict__ A,
                                                        const float* __restrict__ W,
                                                        const float* __restrict__ bias,
                                                        __half* __restrict__ Yh,
                                                        int n_rows) {
    constexpr int BM = 128;
    constexpr int BK = 64;
    constexpr int BN = N;
    constexpr int LDA = BK + 8;
    constexpr int LDB = BN + 8;
    constexpr int WN = BN / 32;
    constexpr int WM = 2;

    __shared__ __half As[BM][LDA];
    __shared__ __half Bs[BK][LDB];
    __shared__ float St[8][16][20];

    const int t = threadIdx.x;
    const int warp = t >> 5;
    const int lane = t & 31;
    const int row0 = blockIdx.x * BM;
    const int warpM = warp & 3;
    const int warpN = warp >> 2;

    wmma::fragment<wmma::accumulator, 16, 16, 16, float> acc[WM][WN];
#pragma unroll
    for (int mi = 0; mi < WM; mi++)
#pragma unroll
        for (int ni = 0; ni < WN; ni++) wmma::fill_fragment(acc[mi][ni], 0.0f);

    for (int k0 = 0; k0 < K; k0 += BK) {
        {
            const int quad = t & 15;
            const int rsub = t >> 4;
#pragma unroll
            for (int p = 0; p < BM / 16; p++) {
                const int row = p * 16 + rsub;
                const int grow = row0 + row;
                float4 av = make_float4(0.f, 0.f, 0.f, 0.f);
                if (grow < n_rows)
                    av = *reinterpret_cast<const float4*>(A + (size_t)grow * K + k0 + quad * 4);
                if (RELU_BIAS) {
                    float4 bv = *reinterpret_cast<const float4*>(bias + k0 + quad * 4);
                    av.x = fmaxf(av.x + bv.x, 0.f);
                    av.y = fmaxf(av.y + bv.y, 0.f);
                    av.z = fmaxf(av.z + bv.z, 0.f);
                    av.w = fmaxf(av.w + bv.w, 0.f);
                }
                __half2 h01 = __float22half2_rn(make_float2(av.x, av.y));
                __half2 h23 = __float22half2_rn(make_float2(av.z, av.w));
                uint2 o;
                o.x = *reinterpret_cast<unsigned*>(&h01);
                o.y = *reinterpret_cast<unsigned*>(&h23);
                *reinterpret_cast<uint2*>(&As[row][quad * 4]) = o;
            }
        }
        {
            constexpr int QPR = BN / 4;
            constexpr int RPP = 256 / QPR;
            const int quad = t % QPR;
            const int rsub = t / QPR;
#pragma unroll
            for (int p = 0; p < BK / RPP; p++) {
                const int row = p * RPP + rsub;
                float4 wv = *reinterpret_cast<const float4*>(W + (size_t)(k0 + row) * BN + quad * 4);
                __half2 h01 = __float22half2_rn(make_float2(wv.x, wv.y));
                __half2 h23 = __float22half2_rn(make_float2(wv.z, wv.w));
                uint2 o;
                o.x = *reinterpret_cast<unsigned*>(&h01);
                o.y = *reinterpret_cast<unsigned*>(&h23);
                *reinterpret_cast<uint2*>(&Bs[row][quad * 4]) = o;
            }
        }
        __syncthreads();

#pragma unroll
        for (int kk = 0; kk < BK; kk += 16) {
            wmma::fragment<wmma::matrix_a, 16, 16, 16, __half, wmma::row_major> af[WM];
            wmma::fragment<wmma::matrix_b, 16, 16, 16, __half, wmma::row_major> bf[WN];
#pragma unroll
            for (int mi = 0; mi < WM; mi++)
                wmma::load_matrix_sync(af[mi], &As[warpM * 32 + mi * 16][kk], LDA);
#pragma unroll
            for (int ni = 0; ni < WN; ni++)
                wmma::load_matrix_sync(bf[ni], &Bs[kk][warpN * (BN / 2) + ni * 16], LDB);
#pragma unroll
            for (int mi = 0; mi < WM; mi++)
#pragma unroll
                for (int ni = 0; ni < WN; ni++)
                    wmma::mma_sync(acc[mi][ni], af[mi], bf[ni], acc[mi][ni]);
        }
        __syncthreads();
    }

#pragma unroll
    for (int mi = 0; mi < WM; mi++) {
#pragma unroll
        for (int ni = 0; ni < WN; ni++) {
            wmma::store_matrix_sync(&St[warp][0][0], acc[mi][ni], 20, wmma::mem_row_major);
            __syncwarp();
            const int r = lane >> 1;
            const int cq = (lane & 1) * 8;
            const int grow = row0 + warpM * 32 + mi * 16 + r;
            if (grow < n_rows) {
                float* sp = &St[warp][r][cq];
                __half2 h0 = __float22half2_rn(make_float2(sp[0], sp[1]));
                __half2 h1 = __float22half2_rn(make_float2(sp[2], sp[3]));
                __half2 h2 = __float22half2_rn(make_float2(sp[4], sp[5]));
                __half2 h3 = __float22half2_rn(make_float2(sp[6], sp[7]));
                uint4 o;
                o.x = *reinterpret_cast<unsigned*>(&h0);
                o.y = *reinterpret_cast<unsigned*>(&h1);
                o.z = *reinterpret_cast<unsigned*>(&h2);
                o.w = *reinterpret_cast<unsigned*>(&h3);
                const int gcol = warpN * (BN / 2) + ni * 16 + cq;
                *reinterpret_cast<uint4*>(Yh + (size_t)grow * N + gcol) = o;
            }
            __syncwarp();
        }
    }
}

// ---------------------------------------------------------------------------
// launch: R12-proven structure (gemm1 forked vs CSR chain; single spmm1,
// single gemm2, single spmm2). Only delta vs R12: 4-edge-unroll SPMMs.
// ---------------------------------------------------------------------------
extern "C" void kernel_launch(void* const* d_in, const int* in_sizes, int n_in,
                              void* d_out, int out_size) {
    const float* x = (const float*)d_in[0];
    const int* adj_rows = (const int*)d_in[1];
    const int* adj_cols = (const int*)d_in[2];
    const float* adj_vals = (const float*)d_in[3];
    const float* W1 = (const float*)d_in[4];
    const float* b1 = (const float*)d_in[5];
    const float* W2 = (const float*)d_in[6];
    const float* b2 = (const float*)d_in[7];
    float* out = (float*)d_out;

    const int n_nodes = in_sizes[0] / 256;
    const int n_edges = in_sizes[1];

    void* yp_ = nullptr;
    void* hp_ = nullptr;
    cudaGetSymbolAddress(&yp_, g_y);
    cudaGetSymbolAddress(&hp_, g_h);
    __half* y = (__half*)yp_;
    float* h = (float*)hp_;
    __half* z = y;  // reuse g_y (fp16) for z after spmm1 consumed y

    static cudaStream_t side = [] {
        cudaStream_t s;
        cudaStreamCreateWithFlags(&s, cudaStreamNonBlocking);
        return s;
    }();
    static cudaEvent_t evFork = [] {
        cudaEvent_t e;
        cudaEventCreateWithFlags(&e, cudaEventDisableTiming);
        return e;
    }();
    static cudaEvent_t evJoin = [] {
        cudaEvent_t e;
        cudaEventCreateWithFlags(&e, cudaEventDisableTiming);
        return e;
    }();

    const int nb_scan = (n_nodes + 1023) / 1024;
    const int eb = (n_edges + 255) / 256;
    const int nb_nodes = (n_nodes + 255) / 256;

    // fork: gemm1 on 'side', concurrent with the CSR chain on stream 0
    cudaEventRecord(evFork, 0);
    cudaStreamWaitEvent(side, evFork, 0);
    wmma_gemm_kernel<256, F1, false>
        <<<(n_nodes + 127) / 128, 256, 0, side>>>(x, W1, nullptr, y, n_nodes);
    cudaEventRecord(evJoin, side);

    // CSR chain (stream 0)
    zero_cnt_kernel<<<nb_nodes, 256>>>(n_nodes);
    hist_kernel<<<eb, 256>>>(adj_rows, n_edges);
    scan1_kernel<<<nb_scan, 256>>>(n_nodes);
    scan23_kernel<<<nb_nodes + 1, 256>>>(n_nodes, n_edges, nb_scan);
    scatter_kernel<<<eb, 256>>>(adj_rows, adj_cols, adj_vals, n_edges);

    // join: spmm1 needs both y (side) and CSR (stream 0)
    cudaStreamWaitEvent(0, evJoin, 0);

    // h = spmm(y) (fp32 accum)
    csr_spmm128_kernel<<<(n_nodes * 32 + 255) / 256, 256>>>(y, h, n_nodes);
    // z = fp16(relu(h + b1) @ W2)
    wmma_gemm_kernel<F1, F2, true><<<(n_nodes + 127) / 128, 256>>>(h, W2, b1, z, n_nodes);
    // out = spmm(z) + b2
    csr_spmm64_kernel<<<(n_nodes * 32 + 255) / 256, 256>>>(z, b2, out, n_nodes);
}

// round 16
// speedup vs baseline: 1.0411x; 1.0298x over previous
#include <cuda_runtime.h>
#include <cuda_fp16.h>
#include <mma.h>
#include <cstdint>

using namespace nvcuda;

#define F1 128
#define F2 64
#define MAX_NODES 100000
#define MAX_EDGES 3200000

// ---------------------------------------------------------------------------
// Device-global scratch (allocation-free per harness rules)
// ---------------------------------------------------------------------------
__device__ __half g_y[(size_t)MAX_NODES * F1];
__device__ float g_h[(size_t)MAX_NODES * F1];
__device__ unsigned long long g_edges[MAX_EDGES]; // packed (col, val) sorted by row
__device__ int g_cnt[MAX_NODES];
__device__ int g_bsum[128];
__device__ int g_flag[128];
__device__ int g_ptr[MAX_NODES + 1];
__device__ int g_work[MAX_NODES];

// ---------------------------------------------------------------------------
// CSR build: zero (counts+flags) -> histogram -> fused single-pass scan -> scatter
// ---------------------------------------------------------------------------
__global__ __launch_bounds__(256) void zero_cnt_kernel(int n_nodes) {
    int i = blockIdx.x * 256 + threadIdx.x;
    if (i < n_nodes) g_cnt[i] = 0;
    if (i < 128) g_flag[i] = 0;
}

__global__ __launch_bounds__(256) void hist_kernel(const int* __restrict__ rows,
                                                   int n_edges) {
    int e = blockIdx.x * 256 + threadIdx.x;
    if (e < n_edges) atomicAdd(&g_cnt[__ldg(rows + e)], 1);
}

// Fused single-pass scan: each block scans its 1024-node chunk, publishes its
// total (fenced flag), gathers predecessor totals in parallel (all blocks are
// co-resident: 98 blocks < 148 SMs), and writes final row ptrs + cursors.
__global__ __launch_bounds__(256) void scan_fused_kernel(int n_nodes, int n_edges) {
    __shared__ int s[256];
    __shared__ int s2[256];
    const int t = threadIdx.x;
    const int chunk = blockIdx.x;
    const int base = chunk * 1024 + t * 4;

    int v[4];
#pragma unroll
    for (int j = 0; j < 4; j++) v[j] = (base + j < n_nodes) ? g_cnt[base + j] : 0;
    int tsum = v[0] + v[1] + v[2] + v[3];
    s[t] = tsum;
    __syncthreads();
    for (int off = 1; off < 256; off <<= 1) {
        int x = 0;
        if (t >= off) x = s[t - off];
        __syncthreads();
        if (t >= off) s[t] += x;
        __syncthreads();
    }
    // publish block total
    if (t == 255) {
        g_bsum[chunk] = s[255];
        __threadfence();
        atomicExch(&g_flag[chunk], 1);
    }
    // parallel lookback: thread t gathers chunk t's total for t < chunk
    int contrib = 0;
    if (t < chunk) {
        while (atomicAdd(&g_flag[t], 0) == 0) {}
        contrib = __ldcg(&g_bsum[t]);
    }
    s2[t] = contrib;
    __syncthreads();
#pragma unroll
    for (int off = 128; off > 0; off >>= 1) {
        if (t < off) s2[t] += s2[t + off];
        __syncthreads();
    }
    const int prefix = s2[0];

    int run = s[t] - tsum + prefix;  // global exclusive prefix
#pragma unroll
    for (int j = 0; j < 4; j++) {
        if (base + j < n_nodes) {
            g_ptr[base + j] = run;
            g_work[base + j] = run;
        }
        run += v[j];
    }
    if (chunk == 0 && t == 0) g_ptr[n_nodes] = n_edges;
}

__global__ __launch_bounds__(256) void scatter_kernel(const int* __restrict__ rows,
                                                      const int* __restrict__ cols,
                                                      const float* __restrict__ vals,
                                                      int n_edges) {
    int e = blockIdx.x * 256 + threadIdx.x;
    if (e < n_edges) {
        int r = __ldg(rows + e);
        int pos = atomicAdd(&g_work[r], 1);
        unsigned long long packed =
            (unsigned long long)(unsigned int)__ldg(cols + e) |
            ((unsigned long long)__float_as_uint(__ldg(vals + e)) << 32);
        g_edges[pos] = packed;
    }
}

// ---------------------------------------------------------------------------
// Pull-based CSR SPMM from fp16 source, fp32 accumulation (R12-proven form).
// ---------------------------------------------------------------------------
__global__ __launch_bounds__(256) void csr_spmm128_kernel(const __half* __restrict__ src,
                                                          float* __restrict__ dst,
                                                          int n_nodes) {
    const int lane = threadIdx.x & 31;
    const int row = (blockIdx.x * 256 + threadIdx.x) >> 5;
    if (row >= n_nodes) return;
    const int p0 = __ldg(&g_ptr[row]);
    const int p1 = __ldg(&g_ptr[row + 1]);
    const uint2* s8 = reinterpret_cast<const uint2*>(src);

    float4 acc = make_float4(0.f, 0.f, 0.f, 0.f);
    int e = p0;
    for (; e + 2 <= p1; e += 2) {
        unsigned long long e0 = __ldg(&g_edges[e]);
        unsigned long long e1 = __ldg(&g_edges[e + 1]);
        int c0 = (int)(unsigned int)e0;
        int c1 = (int)(unsigned int)e1;
        float v0 = __uint_as_float((unsigned int)(e0 >> 32));
        float v1 = __uint_as_float((unsigned int)(e1 >> 32));
        uint2 a = __ldg(s8 + (size_t)c0 * 32 + lane);
        uint2 b = __ldg(s8 + (size_t)c1 * 32 + lane);
        float2 a01 = __half22float2(*reinterpret_cast<__half2*>(&a.x));
        float2 a23 = __half22float2(*reinterpret_cast<__half2*>(&a.y));
        float2 b01 = __half22float2(*reinterpret_cast<__half2*>(&b.x));
        float2 b23 = __half22float2(*reinterpret_cast<__half2*>(&b.y));
        acc.x = fmaf(a01.x, v0, fmaf(b01.x, v1, acc.x));
        acc.y = fmaf(a01.y, v0, fmaf(b01.y, v1, acc.y));
        acc.z = fmaf(a23.x, v0, fmaf(b23.x, v1, acc.z));
        acc.w = fmaf(a23.y, v0, fmaf(b23.y, v1, acc.w));
    }
    if (e < p1) {
        unsigned long long e0 = __ldg(&g_edges[e]);
        int c0 = (int)(unsigned int)e0;
        float v0 = __uint_as_float((unsigned int)(e0 >> 32));
        uint2 a = __ldg(s8 + (size_t)c0 * 32 + lane);
        float2 a01 = __half22float2(*reinterpret_cast<__half2*>(&a.x));
        float2 a23 = __half22float2(*reinterpret_cast<__half2*>(&a.y));
        acc.x = fmaf(a01.x, v0, acc.x);
        acc.y = fmaf(a01.y, v0, acc.y);
        acc.z = fmaf(a23.x, v0, acc.z);
        acc.w = fmaf(a23.y, v0, acc.w);
    }
    reinterpret_cast<float4*>(dst)[(size_t)row * 32 + lane] = acc;
}

__global__ __launch_bounds__(256) void csr_spmm64_kernel(const __half* __restrict__ src,
                                                         const float* __restrict__ b2,
                                                         float* __restrict__ dst,
                                                         int n_nodes) {
    const int lane = threadIdx.x & 31;
    const int row = (blockIdx.x * 256 + threadIdx.x) >> 5;
    if (row >= n_nodes) return;
    const int p0 = __ldg(&g_ptr[row]);
    const int p1 = __ldg(&g_ptr[row + 1]);
    const unsigned* s4 = reinterpret_cast<const unsigned*>(src);

    float2 acc = make_float2(0.f, 0.f);
    int e = p0;
    for (; e + 2 <= p1; e += 2) {
        unsigned long long e0 = __ldg(&g_edges[e]);
        unsigned long long e1 = __ldg(&g_edges[e + 1]);
        int c0 = (int)(unsigned int)e0;
        int c1 = (int)(unsigned int)e1;
        float v0 = __uint_as_float((unsigned int)(e0 >> 32));
        float v1 = __uint_as_float((unsigned int)(e1 >> 32));
        unsigned a = __ldg(s4 + (size_t)c0 * 32 + lane);
        unsigned b = __ldg(s4 + (size_t)c1 * 32 + lane);
        float2 af = __half22float2(*reinterpret_cast<__half2*>(&a));
        float2 bf = __half22float2(*reinterpret_cast<__half2*>(&b));
        acc.x = fmaf(af.x, v0, fmaf(bf.x, v1, acc.x));
        acc.y = fmaf(af.y, v0, fmaf(bf.y, v1, acc.y));
    }
    if (e < p1) {
        unsigned long long e0 = __ldg(&g_edges[e]);
        int c0 = (int)(unsigned int)e0;
        float v0 = __uint_as_float((unsigned int)(e0 >> 32));
        unsigned a = __ldg(s4 + (size_t)c0 * 32 + lane);
        float2 af = __half22float2(*reinterpret_cast<__half2*>(&a));
        acc.x = fmaf(af.x, v0, acc.x);
        acc.y = fmaf(af.y, v0, acc.y);
    }
    float2 bv = __ldg(reinterpret_cast<const float2*>(b2) + lane);
    acc.x += bv.x;
    acc.y += bv.y;
    reinterpret_cast<float2*>(dst)[(size_t)row * 32 + lane] = acc;
}

// ---------------------------------------------------------------------------
// Tensor-core GEMM (wmma m16n16k16, fp16 in / fp32 acc)
// ---------------------------------------------------------------------------
template <int K, int N, bool RELU_BIAS>
__global__ __launch_bounds__(256) void wmma_gemm_kernel(const float* __restrict__ A,
                                                        const float* __restrict__ W,
                                                        const float* __restrict__ bias,
                                                        __half* __restrict__ Yh,
                                                        int n_rows) {
    constexpr int BM = 128;
    constexpr int BK = 64;
    constexpr int BN = N;
    constexpr int LDA = BK + 8;
    constexpr int LDB = BN + 8;
    constexpr int WN = BN / 32;
    constexpr int WM = 2;

    __shared__ __half As[BM][LDA];
    __shared__ __half Bs[BK][LDB];
    __shared__ float St[8][16][20];

    const int t = threadIdx.x;
    const int warp = t >> 5;
    const int lane = t & 31;
    const int row0 = blockIdx.x * BM;
    const int warpM = warp & 3;
    const int warpN = warp >> 2;

    wmma::fragment<wmma::accumulator, 16, 16, 16, float> acc[WM][WN];
#pragma unroll
    for (int mi = 0; mi < WM; mi++)
#pragma unroll
        for (int ni = 0; ni < WN; ni++) wmma::fill_fragment(acc[mi][ni], 0.0f);

    for (int k0 = 0; k0 < K; k0 += BK) {
        {
            const int quad = t & 15;
            const int rsub = t >> 4;
#pragma unroll
            for (int p = 0; p < BM / 16; p++) {
                const int row = p * 16 + rsub;
                const int grow = row0 + row;
                float4 av = make_float4(0.f, 0.f, 0.f, 0.f);
                if (grow < n_rows)
                    av = *reinterpret_cast<const float4*>(A + (size_t)grow * K + k0 + quad * 4);
                if (RELU_BIAS) {
                    float4 bv = *reinterpret_cast<const float4*>(bias + k0 + quad * 4);
                    av.x = fmaxf(av.x + bv.x, 0.f);
                    av.y = fmaxf(av.y + bv.y, 0.f);
                    av.z = fmaxf(av.z + bv.z, 0.f);
                    av.w = fmaxf(av.w + bv.w, 0.f);
                }
                __half2 h01 = __float22half2_rn(make_float2(av.x, av.y));
                __half2 h23 = __float22half2_rn(make_float2(av.z, av.w));
                uint2 o;
                o.x = *reinterpret_cast<unsigned*>(&h01);
                o.y = *reinterpret_cast<unsigned*>(&h23);
                *reinterpret_cast<uint2*>(&As[row][quad * 4]) = o;
            }
        }
        {
            constexpr int QPR = BN / 4;
            constexpr int RPP = 256 / QPR;
            const int quad = t % QPR;
            const int rsub = t / QPR;
#pragma unroll
            for (int p = 0; p < BK / RPP; p++) {
                const int row = p * RPP + rsub;
                float4 wv = *reinterpret_cast<const float4*>(W + (size_t)(k0 + row) * BN + quad * 4);
                __half2 h01 = __float22half2_rn(make_float2(wv.x, wv.y));
                __half2 h23 = __float22half2_rn(make_float2(wv.z, wv.w));
                uint2 o;
                o.x = *reinterpret_cast<unsigned*>(&h01);
                o.y = *reinterpret_cast<unsigned*>(&h23);
                *reinterpret_cast<uint2*>(&Bs[row][quad * 4]) = o;
            }
        }
        __syncthreads();

#pragma unroll
        for (int kk = 0; kk < BK; kk += 16) {
            wmma::fragment<wmma::matrix_a, 16, 16, 16, __half, wmma::row_major> af[WM];
            wmma::fragment<wmma::matrix_b, 16, 16, 16, __half, wmma::row_major> bf[WN];
#pragma unroll
            for (int mi = 0; mi < WM; mi++)
                wmma::load_matrix_sync(af[mi], &As[warpM * 32 + mi * 16][kk], LDA);
#pragma unroll
            for (int ni = 0; ni < WN; ni++)
                wmma::load_matrix_sync(bf[ni], &Bs[kk][warpN * (BN / 2) + ni * 16], LDB);
#pragma unroll
            for (int mi = 0; mi < WM; mi++)
#pragma unroll
                for (int ni = 0; ni < WN; ni++)
                    wmma::mma_sync(acc[mi][ni], af[mi], bf[ni], acc[mi][ni]);
        }
        __syncthreads();
    }

#pragma unroll
    for (int mi = 0; mi < WM; mi++) {
#pragma unroll
        for (int ni = 0; ni < WN; ni++) {
            wmma::store_matrix_sync(&St[warp][0][0], acc[mi][ni], 20, wmma::mem_row_major);
            __syncwarp();
            const int r = lane >> 1;
            const int cq = (lane & 1) * 8;
            const int grow = row0 + warpM * 32 + mi * 16 + r;
            if (grow < n_rows) {
                float* sp = &St[warp][r][cq];
                __half2 h0 = __float22half2_rn(make_float2(sp[0], sp[1]));
                __half2 h1 = __float22half2_rn(make_float2(sp[2], sp[3]));
                __half2 h2 = __float22half2_rn(make_float2(sp[4], sp[5]));
                __half2 h3 = __float22half2_rn(make_float2(sp[6], sp[7]));
                uint4 o;
                o.x = *reinterpret_cast<unsigned*>(&h0);
                o.y = *reinterpret_cast<unsigned*>(&h1);
                o.z = *reinterpret_cast<unsigned*>(&h2);
                o.w = *reinterpret_cast<unsigned*>(&h3);
                const int gcol = warpN * (BN / 2) + ni * 16 + cq;
                *reinterpret_cast<uint4*>(Yh + (size_t)grow * N + gcol) = o;
            }
            __syncwarp();
        }
    }
}

// ---------------------------------------------------------------------------
// launch: R12 structure; only delta = fused single-pass scan (one fewer launch).
// ---------------------------------------------------------------------------
extern "C" void kernel_launch(void* const* d_in, const int* in_sizes, int n_in,
                              void* d_out, int out_size) {
    const float* x = (const float*)d_in[0];
    const int* adj_rows = (const int*)d_in[1];
    const int* adj_cols = (const int*)d_in[2];
    const float* adj_vals = (const float*)d_in[3];
    const float* W1 = (const float*)d_in[4];
    const float* b1 = (const float*)d_in[5];
    const float* W2 = (const float*)d_in[6];
    const float* b2 = (const float*)d_in[7];
    float* out = (float*)d_out;

    const int n_nodes = in_sizes[0] / 256;
    const int n_edges = in_sizes[1];

    void* yp_ = nullptr;
    void* hp_ = nullptr;
    cudaGetSymbolAddress(&yp_, g_y);
    cudaGetSymbolAddress(&hp_, g_h);
    __half* y = (__half*)yp_;
    float* h = (float*)hp_;
    __half* z = y;  // reuse g_y (fp16) for z after spmm1 consumed y

    static cudaStream_t side = [] {
        cudaStream_t s;
        cudaStreamCreateWithFlags(&s, cudaStreamNonBlocking);
        return s;
    }();
    static cudaEvent_t evFork = [] {
        cudaEvent_t e;
        cudaEventCreateWithFlags(&e, cudaEventDisableTiming);
        return e;
    }();
    static cudaEvent_t evJoin = [] {
        cudaEvent_t e;
        cudaEventCreateWithFlags(&e, cudaEventDisableTiming);
        return e;
    }();

    const int nb_scan = (n_nodes + 1023) / 1024;
    const int eb = (n_edges + 255) / 256;
    const int nb_nodes = (n_nodes + 255) / 256;

    // fork: gemm1 on 'side', concurrent with the CSR chain on stream 0
    cudaEventRecord(evFork, 0);
    cudaStreamWaitEvent(side, evFork, 0);
    wmma_gemm_kernel<256, F1, false>
        <<<(n_nodes + 127) / 128, 256, 0, side>>>(x, W1, nullptr, y, n_nodes);
    cudaEventRecord(evJoin, side);

    // CSR chain (stream 0)
    zero_cnt_kernel<<<nb_nodes, 256>>>(n_nodes);
    hist_kernel<<<eb, 256>>>(adj_rows, n_edges);
    scan_fused_kernel<<<nb_scan, 256>>>(n_nodes, n_edges);
    scatter_kernel<<<eb, 256>>>(adj_rows, adj_cols, adj_vals, n_edges);

    // join: spmm1 needs both y (side) and CSR (stream 0)
    cudaStreamWaitEvent(0, evJoin, 0);

    // h = spmm(y) (fp32 accum)
    csr_spmm128_kernel<<<(n_nodes * 32 + 255) / 256, 256>>>(y, h, n_nodes);
    // z = fp16(relu(h + b1) @ W2)
    wmma_gemm_kernel<F1, F2, true><<<(n_nodes + 127) / 128, 256>>>(h, W2, b1, z, n_nodes);
    // out = spmm(z) + b2
    csr_spmm64_kernel<<<(n_nodes * 32 + 255) / 256, 256>>>(z, b2, out, n_nodes);
}

// round 17
// speedup vs baseline: 1.0492x; 1.0078x over previous
#include <cuda_runtime.h>
#include <cuda_fp16.h>
#include <mma.h>
#include <cstdint>

using namespace nvcuda;

#define F1 128
#define F2 64
#define MAX_NODES 100000
#define MAX_EDGES 3200000

// ---------------------------------------------------------------------------
// Device-global scratch (allocation-free per harness rules).
// Invariant: g_cnt and g_flag are all-zero at entry to every call — true on
// call 1 (static zero-init) and re-established within every call (scan zeroes
// g_cnt after consuming it; scatter zeroes g_flag). Identical work each call.
// ---------------------------------------------------------------------------
__device__ __half g_y[(size_t)MAX_NODES * F1];
__device__ float g_h[(size_t)MAX_NODES * F1];
__device__ unsigned long long g_edges[MAX_EDGES]; // packed (col, val) sorted by row
__device__ int g_cnt[MAX_NODES];
__device__ int g_bsum[128];
__device__ int g_flag[128];
__device__ int g_ptr[MAX_NODES + 1];
__device__ int g_work[MAX_NODES];

// ---------------------------------------------------------------------------
// CSR build: histogram -> fused single-pass scan (self-zeroing) -> scatter
// ---------------------------------------------------------------------------
__global__ __launch_bounds__(256) void hist_kernel(const int* __restrict__ rows,
                                                   int n_edges) {
    int e = blockIdx.x * 256 + threadIdx.x;
    if (e < n_edges) atomicAdd(&g_cnt[__ldg(rows + e)], 1);
}

// Fused single-pass scan: each block scans its 1024-node chunk (then zeroes it
// for the next call), publishes its total (fenced flag), gathers predecessor
// totals in parallel (all 98 blocks co-resident < 148 SMs), writes row ptrs +
// scatter cursors.
__global__ __launch_bounds__(256) void scan_fused_kernel(int n_nodes, int n_edges) {
    __shared__ int s[256];
    __shared__ int s2[256];
    const int t = threadIdx.x;
    const int chunk = blockIdx.x;
    const int base = chunk * 1024 + t * 4;

    int v[4];
#pragma unroll
    for (int j = 0; j < 4; j++) v[j] = (base + j < n_nodes) ? g_cnt[base + j] : 0;
    // re-zero counts for the next call (only this thread touches these slots)
#pragma unroll
    for (int j = 0; j < 4; j++)
        if (base + j < n_nodes) g_cnt[base + j] = 0;

    int tsum = v[0] + v[1] + v[2] + v[3];
    s[t] = tsum;
    __syncthreads();
    for (int off = 1; off < 256; off <<= 1) {
        int x = 0;
        if (t >= off) x = s[t - off];
        __syncthreads();
        if (t >= off) s[t] += x;
        __syncthreads();
    }
    // publish block total
    if (t == 255) {
        g_bsum[chunk] = s[255];
        __threadfence();
        atomicExch(&g_flag[chunk], 1);
    }
    // parallel lookback: thread t gathers chunk t's total for t < chunk
    int contrib = 0;
    if (t < chunk) {
        while (atomicAdd(&g_flag[t], 0) == 0) {}
        contrib = __ldcg(&g_bsum[t]);
    }
    s2[t] = contrib;
    __syncthreads();
#pragma unroll
    for (int off = 128; off > 0; off >>= 1) {
        if (t < off) s2[t] += s2[t + off];
        __syncthreads();
    }
    const int prefix = s2[0];

    int run = s[t] - tsum + prefix;  // global exclusive prefix
#pragma unroll
    for (int j = 0; j < 4; j++) {
        if (base + j < n_nodes) {
            g_ptr[base + j] = run;
            g_work[base + j] = run;
        }
        run += v[j];
    }
    if (chunk == 0 && t == 0) g_ptr[n_nodes] = n_edges;
}

__global__ __launch_bounds__(256) void scatter_kernel(const int* __restrict__ rows,
                                                      const int* __restrict__ cols,
                                                      const float* __restrict__ vals,
                                                      int n_edges) {
    // reset scan flags for the next call (scan has fully completed before this
    // kernel launches; only block 0 writes)
    if (blockIdx.x == 0 && threadIdx.x < 128) g_flag[threadIdx.x] = 0;

    int e = blockIdx.x * 256 + threadIdx.x;
    if (e < n_edges) {
        int r = __ldg(rows + e);
        int pos = atomicAdd(&g_work[r], 1);
        unsigned long long packed =
            (unsigned long long)(unsigned int)__ldg(cols + e) |
            ((unsigned long long)__float_as_uint(__ldg(vals + e)) << 32);
        g_edges[pos] = packed;
    }
}

// ---------------------------------------------------------------------------
// Pull-based CSR SPMM from fp16 source, fp32 accumulation (R12-proven form).
// ---------------------------------------------------------------------------
__global__ __launch_bounds__(256) void csr_spmm128_kernel(const __half* __restrict__ src,
                                                          float* __restrict__ dst,
                                                          int n_nodes) {
    const int lane = threadIdx.x & 31;
    const int row = (blockIdx.x * 256 + threadIdx.x) >> 5;
    if (row >= n_nodes) return;
    const int p0 = __ldg(&g_ptr[row]);
    const int p1 = __ldg(&g_ptr[row + 1]);
    const uint2* s8 = reinterpret_cast<const uint2*>(src);

    float4 acc = make_float4(0.f, 0.f, 0.f, 0.f);
    int e = p0;
    for (; e + 2 <= p1; e += 2) {
        unsigned long long e0 = __ldg(&g_edges[e]);
        unsigned long long e1 = __ldg(&g_edges[e + 1]);
        int c0 = (int)(unsigned int)e0;
        int c1 = (int)(unsigned int)e1;
        float v0 = __uint_as_float((unsigned int)(e0 >> 32));
        float v1 = __uint_as_float((unsigned int)(e1 >> 32));
        uint2 a = __ldg(s8 + (size_t)c0 * 32 + lane);
        uint2 b = __ldg(s8 + (size_t)c1 * 32 + lane);
        float2 a01 = __half22float2(*reinterpret_cast<__half2*>(&a.x));
        float2 a23 = __half22float2(*reinterpret_cast<__half2*>(&a.y));
        float2 b01 = __half22float2(*reinterpret_cast<__half2*>(&b.x));
        float2 b23 = __half22float2(*reinterpret_cast<__half2*>(&b.y));
        acc.x = fmaf(a01.x, v0, fmaf(b01.x, v1, acc.x));
        acc.y = fmaf(a01.y, v0, fmaf(b01.y, v1, acc.y));
        acc.z = fmaf(a23.x, v0, fmaf(b23.x, v1, acc.z));
        acc.w = fmaf(a23.y, v0, fmaf(b23.y, v1, acc.w));
    }
    if (e < p1) {
        unsigned long long e0 = __ldg(&g_edges[e]);
        int c0 = (int)(unsigned int)e0;
        float v0 = __uint_as_float((unsigned int)(e0 >> 32));
        uint2 a = __ldg(s8 + (size_t)c0 * 32 + lane);
        float2 a01 = __half22float2(*reinterpret_cast<__half2*>(&a.x));
        float2 a23 = __half22float2(*reinterpret_cast<__half2*>(&a.y));
        acc.x = fmaf(a01.x, v0, acc.x);
        acc.y = fmaf(a01.y, v0, acc.y);
        acc.z = fmaf(a23.x, v0, acc.z);
        acc.w = fmaf(a23.y, v0, acc.w);
    }
    reinterpret_cast<float4*>(dst)[(size_t)row * 32 + lane] = acc;
}

__global__ __launch_bounds__(256) void csr_spmm64_kernel(const __half* __restrict__ src,
                                                         const float* __restrict__ b2,
                                                         float* __restrict__ dst,
                                                         int n_nodes) {
    const int lane = threadIdx.x & 31;
    const int row = (blockIdx.x * 256 + threadIdx.x) >> 5;
    if (row >= n_nodes) return;
    const int p0 = __ldg(&g_ptr[row]);
    const int p1 = __ldg(&g_ptr[row + 1]);
    const unsigned* s4 = reinterpret_cast<const unsigned*>(src);

    float2 acc = make_float2(0.f, 0.f);
    int e = p0;
    for (; e + 2 <= p1; e += 2) {
        unsigned long long e0 = __ldg(&g_edges[e]);
        unsigned long long e1 = __ldg(&g_edges[e + 1]);
        int c0 = (int)(unsigned int)e0;
        int c1 = (int)(unsigned int)e1;
        float v0 = __uint_as_float((unsigned int)(e0 >> 32));
        float v1 = __uint_as_float((unsigned int)(e1 >> 32));
        unsigned a = __ldg(s4 + (size_t)c0 * 32 + lane);
        unsigned b = __ldg(s4 + (size_t)c1 * 32 + lane);
        float2 af = __half22float2(*reinterpret_cast<__half2*>(&a));
        float2 bf = __half22float2(*reinterpret_cast<__half2*>(&b));
        acc.x = fmaf(af.x, v0, fmaf(bf.x, v1, acc.x));
        acc.y = fmaf(af.y, v0, fmaf(bf.y, v1, acc.y));
    }
    if (e < p1) {
        unsigned long long e0 = __ldg(&g_edges[e]);
        int c0 = (int)(unsigned int)e0;
        float v0 = __uint_as_float((unsigned int)(e0 >> 32));
        unsigned a = __ldg(s4 + (size_t)c0 * 32 + lane);
        float2 af = __half22float2(*reinterpret_cast<__half2*>(&a));
        acc.x = fmaf(af.x, v0, acc.x);
        acc.y = fmaf(af.y, v0, acc.y);
    }
    float2 bv = __ldg(reinterpret_cast<const float2*>(b2) + lane);
    acc.x += bv.x;
    acc.y += bv.y;
    reinterpret_cast<float2*>(dst)[(size_t)row * 32 + lane] = acc;
}

// ---------------------------------------------------------------------------
// Tensor-core GEMM (wmma m16n16k16, fp16 in / fp32 acc)
// ---------------------------------------------------------------------------
template <int K, int N, bool RELU_BIAS>
__global__ __launch_bounds__(256) void wmma_gemm_kernel(const float* __restrict__ A,
                                                        const float* __restrict__ W,
                                                        const float* __restrict__ bias,
                                                        __half* __restrict__ Yh,
                                                        int n_rows) {
    constexpr int BM = 128;
    constexpr int BK = 64;
    constexpr int BN = N;
    constexpr int LDA = BK + 8;
    constexpr int LDB = BN + 8;
    constexpr int WN = BN / 32;
    constexpr int WM = 2;

    __shared__ __half As[BM][LDA];
    __shared__ __half Bs[BK][LDB];
    __shared__ float St[8][16][20];

    const int t = threadIdx.x;
    const int warp = t >> 5;
    const int lane = t & 31;
    const int row0 = blockIdx.x * BM;
    const int warpM = warp & 3;
    const int warpN = warp >> 2;

    wmma::fragment<wmma::accumulator, 16, 16, 16, float> acc[WM][WN];
#pragma unroll
    for (int mi = 0; mi < WM; mi++)
#pragma unroll
        for (int ni = 0; ni < WN; ni++) wmma::fill_fragment(acc[mi][ni], 0.0f);

    for (int k0 = 0; k0 < K; k0 += BK) {
        {
            const int quad = t & 15;
            const int rsub = t >> 4;
#pragma unroll
            for (int p = 0; p < BM / 16; p++) {
                const int row = p * 16 + rsub;
                const int grow = row0 + row;
                float4 av = make_float4(0.f, 0.f, 0.f, 0.f);
                if (grow < n_rows)
                    av = *reinterpret_cast<const float4*>(A + (size_t)grow * K + k0 + quad * 4);
                if (RELU_BIAS) {
                    float4 bv = *reinterpret_cast<const float4*>(bias + k0 + quad * 4);
                    av.x = fmaxf(av.x + bv.x, 0.f);
                    av.y = fmaxf(av.y + bv.y, 0.f);
                    av.z = fmaxf(av.z + bv.z, 0.f);
                    av.w = fmaxf(av.w + bv.w, 0.f);
                }
                __half2 h01 = __float22half2_rn(make_float2(av.x, av.y));
                __half2 h23 = __float22half2_rn(make_float2(av.z, av.w));
                uint2 o;
                o.x = *reinterpret_cast<unsigned*>(&h01);
                o.y = *reinterpret_cast<unsigned*>(&h23);
                *reinterpret_cast<uint2*>(&As[row][quad * 4]) = o;
            }
        }
        {
            constexpr int QPR = BN / 4;
            constexpr int RPP = 256 / QPR;
            const int quad = t % QPR;
            const int rsub = t / QPR;
#pragma unroll
            for (int p = 0; p < BK / RPP; p++) {
                const int row = p * RPP + rsub;
                float4 wv = *reinterpret_cast<const float4*>(W + (size_t)(k0 + row) * BN + quad * 4);
                __half2 h01 = __float22half2_rn(make_float2(wv.x, wv.y));
                __half2 h23 = __float22half2_rn(make_float2(wv.z, wv.w));
                uint2 o;
                o.x = *reinterpret_cast<unsigned*>(&h01);
                o.y = *reinterpret_cast<unsigned*>(&h23);
                *reinterpret_cast<uint2*>(&Bs[row][quad * 4]) = o;
            }
        }
        __syncthreads();

#pragma unroll
        for (int kk = 0; kk < BK; kk += 16) {
            wmma::fragment<wmma::matrix_a, 16, 16, 16, __half, wmma::row_major> af[WM];
            wmma::fragment<wmma::matrix_b, 16, 16, 16, __half, wmma::row_major> bf[WN];
#pragma unroll
            for (int mi = 0; mi < WM; mi++)
                wmma::load_matrix_sync(af[mi], &As[warpM * 32 + mi * 16][kk], LDA);
#pragma unroll
            for (int ni = 0; ni < WN; ni++)
                wmma::load_matrix_sync(bf[ni], &Bs[kk][warpN * (BN / 2) + ni * 16], LDB);
#pragma unroll
            for (int mi = 0; mi < WM; mi++)
#pragma unroll
                for (int ni = 0; ni < WN; ni++)
                    wmma::mma_sync(acc[mi][ni], af[mi], bf[ni], acc[mi][ni]);
        }
        __syncthreads();
    }

#pragma unroll
    for (int mi = 0; mi < WM; mi++) {
#pragma unroll
        for (int ni = 0; ni < WN; ni++) {
            wmma::store_matrix_sync(&St[warp][0][0], acc[mi][ni], 20, wmma::mem_row_major);
            __syncwarp();
            const int r = lane >> 1;
            const int cq = (lane & 1) * 8;
            const int grow = row0 + warpM * 32 + mi * 16 + r;
            if (grow < n_rows) {
                float* sp = &St[warp][r][cq];
                __half2 h0 = __float22half2_rn(make_float2(sp[0], sp[1]));
                __half2 h1 = __float22half2_rn(make_float2(sp[2], sp[3]));
                __half2 h2 = __float22half2_rn(make_float2(sp[4], sp[5]));
                __half2 h3 = __float22half2_rn(make_float2(sp[6], sp[7]));
                uint4 o;
                o.x = *reinterpret_cast<unsigned*>(&h0);
                o.y = *reinterpret_cast<unsigned*>(&h1);
                o.z = *reinterpret_cast<unsigned*>(&h2);
                o.w = *reinterpret_cast<unsigned*>(&h3);
                const int gcol = warpN * (BN / 2) + ni * 16 + cq;
                *reinterpret_cast<uint4*>(Yh + (size_t)grow * N + gcol) = o;
            }
            __syncwarp();
        }
    }
}

// ---------------------------------------------------------------------------
// launch: R16 structure minus the zero_cnt launch (folded into scan/scatter).
// ---------------------------------------------------------------------------
extern "C" void kernel_launch(void* const* d_in, const int* in_sizes, int n_in,
                              void* d_out, int out_size) {
    const float* x = (const float*)d_in[0];
    const int* adj_rows = (const int*)d_in[1];
    const int* adj_cols = (const int*)d_in[2];
    const float* adj_vals = (const float*)d_in[3];
    const float* W1 = (const float*)d_in[4];
    const float* b1 = (const float*)d_in[5];
    const float* W2 = (const float*)d_in[6];
    const float* b2 = (const float*)d_in[7];
    float* out = (float*)d_out;

    const int n_nodes = in_sizes[0] / 256;
    const int n_edges = in_sizes[1];

    void* yp_ = nullptr;
    void* hp_ = nullptr;
    cudaGetSymbolAddress(&yp_, g_y);
    cudaGetSymbolAddress(&hp_, g_h);
    __half* y = (__half*)yp_;
    float* h = (float*)hp_;
    __half* z = y;  // reuse g_y (fp16) for z after spmm1 consumed y

    static cudaStream_t side = [] {
        cudaStream_t s;
        cudaStreamCreateWithFlags(&s, cudaStreamNonBlocking);
        return s;
    }();
    static cudaEvent_t evFork = [] {
        cudaEvent_t e;
        cudaEventCreateWithFlags(&e, cudaEventDisableTiming);
        return e;
    }();
    static cudaEvent_t evJoin = [] {
        cudaEvent_t e;
        cudaEventCreateWithFlags(&e, cudaEventDisableTiming);
        return e;
    }();

    const int nb_scan = (n_nodes + 1023) / 1024;
    const int eb = (n_edges + 255) / 256;

    // fork: gemm1 on 'side', concurrent with the CSR chain on stream 0
    cudaEventRecord(evFork, 0);
    cudaStreamWaitEvent(side, evFork, 0);
    wmma_gemm_kernel<256, F1, false>
        <<<(n_nodes + 127) / 128, 256, 0, side>>>(x, W1, nullptr, y, n_nodes);
    cudaEventRecord(evJoin, side);

    // CSR chain (stream 0): hist -> scan (self-zeroing) -> scatter (flag reset)
    hist_kernel<<<eb, 256>>>(adj_rows, n_edges);
    scan_fused_kernel<<<nb_scan, 256>>>(n_nodes, n_edges);
    scatter_kernel<<<eb, 256>>>(adj_rows, adj_cols, adj_vals, n_edges);

    // join: spmm1 needs both y (side) and CSR (stream 0)
    cudaStreamWaitEvent(0, evJoin, 0);

    // h = spmm(y) (fp32 accum)
    csr_spmm128_kernel<<<(n_nodes * 32 + 255) / 256, 256>>>(y, h, n_nodes);
    // z = fp16(relu(h + b1) @ W2)
    wmma_gemm_kernel<F1, F2, true><<<(n_nodes + 127) / 128, 256>>>(h, W2, b1, z, n_nodes);
    // out = spmm(z) + b2
    csr_spmm64_kernel<<<(n_nodes * 32 + 255) / 256, 256>>>(z, b2, out, n_nodes);
}